// round 2
// baseline (speedup 1.0000x reference)
#include <cuda_runtime.h>
#include <math.h>

// ---------------- scratch (static device globals; no allocation) ----------------
__device__ float g_part1[800 * 2048];          // gemm1 partials: [(j*8+r)][chunk]
__device__ float g_tmp1[800];                  // (8,100) row-major r*100+j
__device__ float g_bn[32];                     // boxNew (8,4)
__device__ float g_feat[8 * 24576];            // pooled features (B, 3*64*128)
__device__ float g_part2[7 * 128 * 8 * 512];   // head partials: [((k*128+h)*8+r)][chunk]
__device__ float g_hidden[7 * 8 * 128];        // relu hidden (k,b,h)

// ---------------- stage 1: xf(8x65536) @ wr2_w1(65536x100), split-K ----------------
// 512 blocks x 128 thr. Block covers 128 K-rows. 100 active threads:
// k_sub = tid/25 in [0,4), j4 = tid%25 -> thread loads float4 of W row (25 f4/row).
// 100 lanes cover exactly 4 contiguous W rows (1600B) -> perfectly coalesced LDG.128.
__global__ void __launch_bounds__(128) k_gemm1_part(const float* __restrict__ x3,
                                                    const float* __restrict__ w1) {
    __shared__ __align__(16) float xs[8 * 128];
    const int bx = blockIdx.x;
    const int k0 = bx * 128;
    const int tid = threadIdx.x;

    const float4* x4 = (const float4*)x3;
    float4* xs4 = (float4*)xs;
    for (int t = tid; t < 256; t += 128) {
        int r = t >> 5, q = t & 31;
        xs4[t] = x4[r * 16384 + (k0 >> 2) + q];
    }
    __syncthreads();

    if (tid < 100) {
        const int ks = tid / 25;
        const int j4 = tid - ks * 25;
        const float4* w4 = (const float4*)w1;
        float acc[8][4] = {};
#pragma unroll 8
        for (int t = 0; t < 32; t++) {
            int kk = ks + 4 * t;
            float4 wv = w4[(size_t)(k0 + kk) * 25 + j4];
#pragma unroll
            for (int r = 0; r < 8; r++) {
                float f = xs[r * 128 + kk];
                acc[r][0] = fmaf(f, wv.x, acc[r][0]);
                acc[r][1] = fmaf(f, wv.y, acc[r][1]);
                acc[r][2] = fmaf(f, wv.z, acc[r][2]);
                acc[r][3] = fmaf(f, wv.w, acc[r][3]);
            }
        }
        const int cb = bx * 4 + ks;   // 2048 chunks
#pragma unroll
        for (int jj = 0; jj < 4; jj++)
#pragma unroll
            for (int r = 0; r < 8; r++)
                g_part1[((j4 * 4 + jj) * 8 + r) * 2048 + cb] = acc[r][jj];
    }
}

__global__ void k_reduce_g1(const float* __restrict__ b1) {
    int w = (blockIdx.x * blockDim.x + threadIdx.x) >> 5;  // 800 warps
    int lane = threadIdx.x & 31;
    if (w >= 800) return;
    const float* p = &g_part1[w * 2048];
    float s = 0.f;
#pragma unroll
    for (int q = 0; q < 64; q++) s += p[lane + q * 32];
#pragma unroll
    for (int o = 16; o; o >>= 1) s += __shfl_down_sync(0xffffffffu, s, o);
    if (lane == 0) {
        int j = w >> 3, r = w & 7;
        g_tmp1[r * 100 + j] = s + b1[j];
    }
}

// ---------------- stage 2: tiny MLP -> boxLoc -> boxNew, one block per batch row ----
__global__ void __launch_bounds__(128) k_mlp_box(const float* __restrict__ w2,
                                                 const float* __restrict__ b2,
                                                 const float* __restrict__ w3,
                                                 const float* __restrict__ b3) {
    __shared__ __align__(16) float w2s[10000];
    __shared__ float t1[100], t2[104], bl[4];
    const int b = blockIdx.x;
    const int tid = threadIdx.x;

    if (tid < 100) t1[tid] = g_tmp1[b * 100 + tid];
    const float4* w24 = (const float4*)w2;
    float4* w2s4 = (float4*)w2s;
    for (int t = tid; t < 2500; t += 128) w2s4[t] = w24[t];
    __syncthreads();

    if (tid < 100) {
        float acc = b2[tid];
#pragma unroll 4
        for (int i = 0; i < 100; i++) acc = fmaf(t1[i], w2s[i * 100 + tid], acc);
        t2[tid] = acc;
    }
    __syncthreads();
    if (tid < 4) {
        float acc = b3[tid];
#pragma unroll 4
        for (int i = 0; i < 100; i++) acc = fmaf(t2[i], w3[i * 4 + tid], acc);
        bl[tid] = acc;
    }
    __syncthreads();
    if (tid < 4) {
        float v;
        if (tid == 0)      v = bl[0] - 0.5f * bl[2];
        else if (tid == 1) v = bl[1] - 0.5f * bl[3];
        else if (tid == 2) v = bl[0] + 0.5f * bl[2];
        else               v = bl[1] + 0.5f * bl[3];
        g_bn[b * 4 + tid] = fminf(fmaxf(v, 0.0f), 1.0f);
    }
}

// ---------------- stage 3: ROI adaptive max-pool via smem staging ----------------
// Grid 2048: bx<1024 -> s=0 (2 half-blocks per (b,c)); [1024,1536) s=1; [1536,2048) s=2.
// Box rows loaded coalesced (warp per row) into smem, then per-bin max from smem.
__global__ void __launch_bounds__(128) k_roi(const float* __restrict__ x1p,
                                             const float* __restrict__ x2p,
                                             const float* __restrict__ x3p) {
    __shared__ float sm[8320];   // 33.3KB: covers worst case 64 rows x 128 cols (+pad)
    const int bx = blockIdx.x;
    int s, nh, half, idx;
    if (bx < 1024)      { s = 0; nh = 2; half = bx & 1; idx = bx >> 1; }
    else if (bx < 1536) { s = 1; nh = 1; half = 0; idx = bx - 1024; }
    else                { s = 2; nh = 1; half = 0; idx = bx - 1536; }
    const int b = idx >> 6, c = idx & 63;
    const int HW = 128 >> s;
    const float* xp = (s == 0) ? x1p : (s == 1) ? x2p : x3p;

    const float Sf = (float)HW;
    const int X1 = (int)floorf(g_bn[b * 4 + 0] * Sf);
    const int Y1 = (int)floorf(g_bn[b * 4 + 1] * Sf);
    const int X2 = (int)floorf(g_bn[b * 4 + 2] * Sf);
    const int Y2 = (int)floorf(g_bn[b * 4 + 3] * Sf);
    const bool valid = (X2 < HW) && (Y2 < HW) && (X2 > X1) && (Y2 > Y1);

    const int tid = threadIdx.x;
    const int bi = 16 / nh;             // i-bins handled by this block
    const int i0 = half * bi;

    float out = 0.0f;
    int i = 0, j = 0;
    bool mine = false;
    if (valid) {
        const int h = Y2 - Y1 + 1, w = X2 - X1 + 1;
        // rows needed for bins [i0, i0+bi)
        const int ylo = (i0 * h) >> 4;
        const int yhi = ((i0 + bi) * h + 15) >> 4;   // exclusive
        const int wid = tid >> 5, lane = tid & 31;
        const float* base = xp + ((size_t)(b * 64 + c) * HW + Y1) * HW + X1;
        for (int y = ylo + wid; y < yhi; y += 4) {
            const float* row = base + y * HW;
            float* srow = sm + (y - ylo) * w;
            for (int x = lane; x < w; x += 32) srow[x] = row[x];
        }
        __syncthreads();
        if (tid < bi * 8) {
            mine = true;
            i = i0 + (tid >> 3); j = tid & 7;
            const int lo_i = (i * h) >> 4, hi_i = ((i + 1) * h + 15) >> 4;
            const int lo_j = (j * w) >> 3, hi_j = ((j + 1) * w + 7) >> 3;
            float m = -3.0e38f;
            for (int y = lo_i; y < hi_i; y++) {
                const float* srow = sm + (y - ylo) * w;
                for (int xx = lo_j; xx < hi_j; xx++) m = fmaxf(m, srow[xx]);
            }
            out = m;
        }
    } else if (tid < bi * 8) {
        mine = true;
        i = i0 + (tid >> 3); j = tid & 7;
    }
    if (mine) g_feat[b * 24576 + (s * 64 + c) * 128 + i * 8 + j] = out;
}

// ---------------- stage 4: feat(8x24576) @ head_w1[k](24576x128), split-K x7 --------
// 896 blocks (7k x 128 chunks of 192 d). Warp wq owns 48 d; thread owns 4 h-cols
// via float4 W loads (48 independent LDG.128 per thread).
__global__ void __launch_bounds__(128) k_head_part(const float* __restrict__ hw) {
    __shared__ __align__(16) float fs[8 * 192];
    const int bx = blockIdx.x;
    const int k = bx >> 7, ch = bx & 127;
    const int d0 = ch * 192;
    const int tid = threadIdx.x;

    const float4* f4 = (const float4*)g_feat;
    float4* fs4 = (float4*)fs;
    for (int t = tid; t < 384; t += 128) {
        int r = t / 48, q = t - r * 48;
        fs4[t] = f4[r * 6144 + ch * 48 + q];
    }
    __syncthreads();

    const int wq = tid >> 5, h4 = tid & 31;
    const float4* w4 = (const float4*)hw;
    const size_t wbase = ((size_t)k * 24576 + d0 + wq * 48) * 32 + h4;
    float acc[8][4] = {};
#pragma unroll 8
    for (int dd = 0; dd < 48; dd++) {
        float4 wv = w4[wbase + (size_t)dd * 32];
        const int fi = wq * 48 + dd;
#pragma unroll
        for (int r = 0; r < 8; r++) {
            float f = fs[r * 192 + fi];
            acc[r][0] = fmaf(f, wv.x, acc[r][0]);
            acc[r][1] = fmaf(f, wv.y, acc[r][1]);
            acc[r][2] = fmaf(f, wv.z, acc[r][2]);
            acc[r][3] = fmaf(f, wv.w, acc[r][3]);
        }
    }
    const int cb = ch * 4 + wq;   // 512 chunks
#pragma unroll
    for (int jj = 0; jj < 4; jj++) {
        const int hcol = h4 * 4 + jj;
#pragma unroll
        for (int r = 0; r < 8; r++)
            g_part2[((k * 128 + hcol) * 8 + r) * 512 + cb] = acc[r][jj];
    }
}

__global__ void k_reduce_head(const float* __restrict__ hb) {
    int w = (blockIdx.x * blockDim.x + threadIdx.x) >> 5;  // 7168 warps
    int lane = threadIdx.x & 31;
    if (w >= 7168) return;
    const float* p = &g_part2[w * 512];
    float s = 0.f;
#pragma unroll
    for (int q = 0; q < 16; q++) s += p[lane + q * 32];
#pragma unroll
    for (int o = 16; o; o >>= 1) s += __shfl_down_sync(0xffffffffu, s, o);
    if (lane == 0) {
        int k = w >> 10, rem = w & 1023, h = rem >> 3, r = rem & 7;
        float v = s + hb[k * 128 + h];
        g_hidden[(k * 8 + r) * 128 + h] = fmaxf(v, 0.0f);
    }
}

// ---------------- stage 5: output heads, one block per (k,b) ----------------
__global__ void __launch_bounds__(64) k_final(const float* __restrict__ wp, const float* __restrict__ bp,
                                              const float* __restrict__ wa, const float* __restrict__ ba,
                                              const float* __restrict__ wad, const float* __restrict__ bad,
                                              float* __restrict__ out) {
    __shared__ float hs[128];
    const int kb = blockIdx.x;    // 56
    const int k = kb >> 3, b = kb & 7;
    int O, off;
    const float *Wk, *Bk;
    if (k == 0)      { O = 38; Wk = wp; Bk = bp; off = 0; }
    else if (k == 1) { O = 25; Wk = wa; Bk = ba; off = 304; }
    else             { O = 35; Wk = wad + (k - 2) * 128 * 35; Bk = bad + (k - 2) * 35;
                       off = 504 + (k - 2) * 280; }
    const int tid = threadIdx.x;
    hs[tid] = g_hidden[(k * 8 + b) * 128 + tid];
    hs[tid + 64] = g_hidden[(k * 8 + b) * 128 + tid + 64];
    __syncthreads();
    if (tid < O) {
        float acc = Bk[tid];
#pragma unroll 4
        for (int h = 0; h < 128; h++) acc = fmaf(hs[h], Wk[h * O + tid], acc);
        out[off + b * O + tid] = acc;
    }
}

// ---------------- launch ----------------
extern "C" void kernel_launch(void* const* d_in, const int* in_sizes, int n_in,
                              void* d_out, int out_size) {
    (void)in_sizes; (void)n_in; (void)out_size;
    const float* x1 = (const float*)d_in[0];
    const float* x2 = (const float*)d_in[1];
    const float* x3 = (const float*)d_in[2];
    const float* w1 = (const float*)d_in[5];
    const float* b1 = (const float*)d_in[6];
    const float* w2 = (const float*)d_in[7];
    const float* b2 = (const float*)d_in[8];
    const float* w3 = (const float*)d_in[9];
    const float* b3 = (const float*)d_in[10];
    const float* hw = (const float*)d_in[11];
    const float* hb = (const float*)d_in[12];
    const float* wp = (const float*)d_in[13];
    const float* bp = (const float*)d_in[14];
    const float* wa = (const float*)d_in[15];
    const float* ba = (const float*)d_in[16];
    const float* wad = (const float*)d_in[17];
    const float* bad = (const float*)d_in[18];
    float* out = (float*)d_out;

    k_gemm1_part<<<512, 128>>>(x3, w1);
    k_reduce_g1<<<100, 256>>>(b1);
    k_mlp_box<<<8, 128>>>(w2, b2, w3, b3);
    k_roi<<<2048, 128>>>(x1, x2, x3);
    k_head_part<<<896, 128>>>(hw);
    k_reduce_head<<<896, 256>>>(hb);
    k_final<<<56, 64>>>(wp, bp, wa, ba, wad, bad, out);
}

// round 3
// speedup vs baseline: 1.1991x; 1.1991x over previous
#include <cuda_runtime.h>
#include <math.h>

// ---------------- scratch (static device globals; no allocation) ----------------
__device__ float g_part1[1024 * 800];          // gemm1 partials: [chunk][j*8+r]
__device__ float g_tmp1[800];                  // (8,100) row-major r*100+j
__device__ float g_bn[32];                     // boxNew (8,4)
__device__ float g_feat[8 * 24576];            // pooled features (B, 3*64*128)
__device__ float g_part2[7 * 128 * 8 * 128];   // head partials: [k][ch][r][h]

// ---------------- stage 1: xf(8x65536) @ wr2_w1(65536x100), split-K ----------------
// 1024 blocks x 128 thr; block covers 64 K-rows. 100 active threads:
// ks=tid/25 selects k-phase, j4=tid%25 selects float4 of the 100-wide W row.
// In-block reduce over the 4 k-phases -> ONE coalesced 800-float chunk write.
__global__ void __launch_bounds__(128) k_gemm1_part(const float* __restrict__ x3,
                                                    const float* __restrict__ w1) {
    __shared__ __align__(16) float xs[8 * 64];
    __shared__ float red[4 * 800];
    const int bx = blockIdx.x;
    const int k0 = bx * 64;
    const int tid = threadIdx.x;

    const float4* x4 = (const float4*)x3;
    float4* xs4 = (float4*)xs;
    {   // 128 float4 loads, one per thread
        int r = tid >> 4, q = tid & 15;
        xs4[tid] = x4[r * 16384 + bx * 16 + q];
    }
    __syncthreads();

    if (tid < 100) {
        const int ks = tid / 25;
        const int j4 = tid - ks * 25;
        const float4* w4 = (const float4*)w1;
        float acc[8][4] = {};
#pragma unroll
        for (int t = 0; t < 16; t++) {
            int kk = ks + 4 * t;
            float4 wv = w4[(size_t)(k0 + kk) * 25 + j4];
#pragma unroll
            for (int r = 0; r < 8; r++) {
                float f = xs[r * 64 + kk];
                acc[r][0] = fmaf(f, wv.x, acc[r][0]);
                acc[r][1] = fmaf(f, wv.y, acc[r][1]);
                acc[r][2] = fmaf(f, wv.z, acc[r][2]);
                acc[r][3] = fmaf(f, wv.w, acc[r][3]);
            }
        }
#pragma unroll
        for (int jj = 0; jj < 4; jj++)
#pragma unroll
            for (int r = 0; r < 8; r++)
                red[ks * 800 + (j4 * 4 + jj) * 8 + r] = acc[r][jj];
    }
    __syncthreads();
    for (int t = tid; t < 800; t += 128) {
        float s = red[t] + red[800 + t] + red[1600 + t] + red[2400 + t];
        g_part1[(size_t)bx * 800 + t] = s;   // coalesced
    }
}

// 25 blocks x 256 thr: out = bx*32 + lane, 8 chunk-groups per block.
__global__ void __launch_bounds__(256) k_reduce_g1(const float* __restrict__ b1) {
    __shared__ float red[256];
    const int tid = threadIdx.x;
    const int out = blockIdx.x * 32 + (tid & 31);
    const int cq = tid >> 5;
    float s = 0.f;
#pragma unroll 8
    for (int q = 0; q < 128; q++) s += g_part1[(size_t)(cq + 8 * q) * 800 + out];
    red[tid] = s;
    __syncthreads();
    if (tid < 32) {
        int o = blockIdx.x * 32 + tid;
        float t = red[tid];
#pragma unroll
        for (int c = 1; c < 8; c++) t += red[c * 32 + tid];
        g_tmp1[(o & 7) * 100 + (o >> 3)] = t + b1[o >> 3];
    }
}

// ---------------- stage 2: tiny MLP -> boxLoc -> boxNew, one block per batch row ----
__global__ void __launch_bounds__(128) k_mlp_box(const float* __restrict__ w2,
                                                 const float* __restrict__ b2,
                                                 const float* __restrict__ w3,
                                                 const float* __restrict__ b3) {
    __shared__ __align__(16) float w2s[10000];
    __shared__ float t1[100], t2[104], bl[4];
    const int b = blockIdx.x;
    const int tid = threadIdx.x;

    if (tid < 100) t1[tid] = g_tmp1[b * 100 + tid];
    const float4* w24 = (const float4*)w2;
    float4* w2s4 = (float4*)w2s;
    for (int t = tid; t < 2500; t += 128) w2s4[t] = w24[t];
    __syncthreads();

    if (tid < 100) {
        float acc = b2[tid];
#pragma unroll 4
        for (int i = 0; i < 100; i++) acc = fmaf(t1[i], w2s[i * 100 + tid], acc);
        t2[tid] = acc;
    }
    __syncthreads();
    if (tid < 4) {
        float acc = b3[tid];
#pragma unroll 4
        for (int i = 0; i < 100; i++) acc = fmaf(t2[i], w3[i * 4 + tid], acc);
        bl[tid] = acc;
    }
    __syncthreads();
    if (tid < 4) {
        float v;
        if (tid == 0)      v = bl[0] - 0.5f * bl[2];
        else if (tid == 1) v = bl[1] - 0.5f * bl[3];
        else if (tid == 2) v = bl[0] + 0.5f * bl[2];
        else               v = bl[1] + 0.5f * bl[3];
        g_bn[b * 4 + tid] = fminf(fmaxf(v, 0.0f), 1.0f);
    }
}

// ---------------- stage 3: ROI two-pass (column-max then bin-max) ----------------
// 1536 blocks (s,b,c), 128 thr. Pass A: thread per column x, computes the 16
// per-row-bin column maxes with fully coalesced row reads (each element once).
// Pass B: thread per bin maxes over smem column range. smem = 8KB.
__global__ void __launch_bounds__(128) k_roi(const float* __restrict__ x1p,
                                             const float* __restrict__ x2p,
                                             const float* __restrict__ x3p) {
    __shared__ float cm[16 * 128];
    const int bx = blockIdx.x;
    const int s = bx >> 9;
    const int rem = bx & 511;
    const int b = rem >> 6, c = rem & 63;
    const int HW = 128 >> s;
    const float* xp = (s == 0) ? x1p : (s == 1) ? x2p : x3p;

    const float Sf = (float)HW;
    const int X1 = (int)floorf(g_bn[b * 4 + 0] * Sf);
    const int Y1 = (int)floorf(g_bn[b * 4 + 1] * Sf);
    const int X2 = (int)floorf(g_bn[b * 4 + 2] * Sf);
    const int Y2 = (int)floorf(g_bn[b * 4 + 3] * Sf);
    const bool valid = (X2 < HW) && (Y2 < HW) && (X2 > X1) && (Y2 > Y1);

    const int tid = threadIdx.x;
    float* gout = &g_feat[b * 24576 + (s * 64 + c) * 128];
    if (!valid) { gout[tid] = 0.f; return; }

    const int h = Y2 - Y1 + 1, w = X2 - X1 + 1;
    const float* base = xp + ((size_t)(b * 64 + c) * HW + Y1) * HW + X1;

    if (tid < w) {
#pragma unroll 1
        for (int i = 0; i < 16; i++) {
            const int ylo = (i * h) >> 4, yhi = ((i + 1) * h + 15) >> 4;
            float m = -3.0e38f;
            for (int y = ylo; y < yhi; y++) m = fmaxf(m, base[(size_t)y * HW + tid]);
            cm[i * 128 + tid] = m;
        }
    }
    __syncthreads();
    const int i = tid >> 3, j = tid & 7;
    const int lo = (j * w) >> 3, hi = ((j + 1) * w + 7) >> 3;
    float m = -3.0e38f;
    for (int x = lo; x < hi; x++) m = fmaxf(m, cm[i * 128 + x]);
    gout[tid] = m;
}

// ---------------- stage 4: feat(8x24576) @ head_w1[k](24576x128), split-K x7 --------
// 896 blocks (7k x 128 chunks of 192 d), 256 thr (8 warps). Warp owns 24 d,
// thread owns 4 h-cols via LDG.128. Cross-warp smem reduce -> one coalesced
// float4 chunk write per thread. 48 warps/SM resident.
__global__ void __launch_bounds__(256) k_head_part(const float* __restrict__ hw) {
    __shared__ __align__(16) float fs[8 * 192];
    __shared__ __align__(16) float red[8 * 1024];
    const int bx = blockIdx.x;
    const int k = bx >> 7, ch = bx & 127;
    const int d0 = ch * 192;
    const int tid = threadIdx.x;

    const float4* f4 = (const float4*)g_feat;
    float4* fs4 = (float4*)fs;
    for (int t = tid; t < 384; t += 256) {
        int r = t / 48, q = t - r * 48;
        fs4[t] = f4[r * 6144 + ch * 48 + q];
    }
    __syncthreads();

    const int wq = tid >> 5, lane = tid & 31;
    const float4* w4 = (const float4*)hw;
    const size_t wbase = ((size_t)k * 24576 + d0 + wq * 24) * 32 + lane;
    float acc[8][4] = {};
#pragma unroll
    for (int dd = 0; dd < 24; dd++) {
        float4 wv = w4[wbase + (size_t)dd * 32];
        const int fi = wq * 24 + dd;
#pragma unroll
        for (int r = 0; r < 8; r++) {
            float f = fs[r * 192 + fi];
            acc[r][0] = fmaf(f, wv.x, acc[r][0]);
            acc[r][1] = fmaf(f, wv.y, acc[r][1]);
            acc[r][2] = fmaf(f, wv.z, acc[r][2]);
            acc[r][3] = fmaf(f, wv.w, acc[r][3]);
        }
    }
    float* myred = red + wq * 1024;
#pragma unroll
    for (int r = 0; r < 8; r++) {
        float4 v = make_float4(acc[r][0], acc[r][1], acc[r][2], acc[r][3]);
        *(float4*)&myred[r * 128 + lane * 4] = v;
    }
    __syncthreads();
    float4 s = *(const float4*)&red[tid * 4];
#pragma unroll
    for (int w = 1; w < 8; w++) {
        float4 t4 = *(const float4*)&red[w * 1024 + tid * 4];
        s.x += t4.x; s.y += t4.y; s.z += t4.z; s.w += t4.w;
    }
    const int r = tid >> 5, hcol = (tid & 31) * 4;
    *(float4*)&g_part2[(((size_t)k * 128 + ch) * 8 + r) * 128 + hcol] = s;  // coalesced
}

// ---------------- stage 5: reduce chunks + bias + relu + output heads (fused) -------
// 56 blocks (k,b), 128 thr (thread = h). Coalesced chunk reads, hidden stays in smem.
__global__ void __launch_bounds__(128) k_head_final(
        const float* __restrict__ hb,
        const float* __restrict__ wp, const float* __restrict__ bp,
        const float* __restrict__ wa, const float* __restrict__ ba,
        const float* __restrict__ wad, const float* __restrict__ bad,
        float* __restrict__ out) {
    __shared__ float hs[128];
    const int kb = blockIdx.x;
    const int k = kb >> 3, b = kb & 7;
    const int tid = threadIdx.x;

    float s = 0.f;
#pragma unroll 8
    for (int ch = 0; ch < 128; ch++)
        s += g_part2[(((size_t)k * 128 + ch) * 8 + b) * 128 + tid];
    s += hb[k * 128 + tid];
    hs[tid] = fmaxf(s, 0.f);
    __syncthreads();

    int O, off;
    const float *Wk, *Bk;
    if (k == 0)      { O = 38; Wk = wp; Bk = bp; off = 0; }
    else if (k == 1) { O = 25; Wk = wa; Bk = ba; off = 304; }
    else             { O = 35; Wk = wad + (k - 2) * 128 * 35; Bk = bad + (k - 2) * 35;
                       off = 504 + (k - 2) * 280; }
    if (tid < O) {
        float acc = Bk[tid];
#pragma unroll 4
        for (int h = 0; h < 128; h++) acc = fmaf(hs[h], Wk[h * O + tid], acc);
        out[off + b * O + tid] = acc;
    }
}

// ---------------- launch ----------------
extern "C" void kernel_launch(void* const* d_in, const int* in_sizes, int n_in,
                              void* d_out, int out_size) {
    (void)in_sizes; (void)n_in; (void)out_size;
    const float* x1 = (const float*)d_in[0];
    const float* x2 = (const float*)d_in[1];
    const float* x3 = (const float*)d_in[2];
    const float* w1 = (const float*)d_in[5];
    const float* b1 = (const float*)d_in[6];
    const float* w2 = (const float*)d_in[7];
    const float* b2 = (const float*)d_in[8];
    const float* w3 = (const float*)d_in[9];
    const float* b3 = (const float*)d_in[10];
    const float* hw = (const float*)d_in[11];
    const float* hb = (const float*)d_in[12];
    const float* wp = (const float*)d_in[13];
    const float* bp = (const float*)d_in[14];
    const float* wa = (const float*)d_in[15];
    const float* ba = (const float*)d_in[16];
    const float* wad = (const float*)d_in[17];
    const float* bad = (const float*)d_in[18];
    float* out = (float*)d_out;

    k_gemm1_part<<<1024, 128>>>(x3, w1);
    k_reduce_g1<<<25, 256>>>(b1);
    k_mlp_box<<<8, 128>>>(w2, b2, w3, b3);
    k_roi<<<1536, 128>>>(x1, x2, x3);
    k_head_part<<<896, 256>>>(hw);
    k_head_final<<<56, 128>>>(hb, wp, bp, wa, ba, wad, bad, out);
}